// round 3
// baseline (speedup 1.0000x reference)
#include <cuda_runtime.h>

// x1:   (16, 1, 224, 224) fp32
// W:    (288, 1, 3, 3)    fp32
// bias: (1, 288, 222, 222) fp32
// out:  (16, 288, 222, 222) fp32 = relu(conv_valid(x1, W) + bias)

#define B_      16
#define COUT_   288
#define CSPLIT  2
#define CPER    (COUT_ / CSPLIT)    // 144 channels per CTA
#define HIN_    224
#define WIN_    224
#define HOUT_   222
#define WOUT_   222
#define PLANE_  (HOUT_ * WOUT_)     // 49284
#define RPB     6                   // output rows per CTA (222 = 37*6)
#define IROWS   (RPB + 2)           // 8 input rows

__global__ __launch_bounds__(224, 8) void conv_bias_relu_kernel(
    const float* __restrict__ x,
    const float* __restrict__ Wt,
    const float* __restrict__ bias,
    float* __restrict__ out)
{
    // Weights padded to 12 floats/channel: per channel = 2x LDS.128 + 1x LDS.32.
    __shared__ __align__(16) float sW[CPER * 12];    // 6912 B
    __shared__ float sIn[IROWS][WIN_];               // 7168 B

    const int hg = blockIdx.x;            // 0..36  (row group)
    const int b  = blockIdx.y;            // 0..15
    const int cg = blockIdx.z;            // 0..1   (channel half)
    const int t  = threadIdx.x;           // 0..223
    const int h0 = hg * RPB;
    const int c0 = cg * CPER;

    // Cooperative weight load (this CTA's 144 channels) with 9->12 padding.
    const float* wsrc = Wt + c0 * 9;
    for (int i = t; i < CPER * 9; i += 224) {
        int c = i / 9, j = i - c * 9;
        sW[c * 12 + j] = wsrc[i];
    }

    // Cooperative load of the 8 input rows this CTA needs (each thread = 1 col).
    const float* xb = x + (long)b * HIN_ * WIN_;
    #pragma unroll
    for (int r = 0; r < IROWS; r++) sIn[r][t] = xb[(h0 + r) * WIN_ + t];

    __syncthreads();

    if (t >= WOUT_) return;

    // 24 taps in registers: rows h0..h0+7, cols t..t+2. Invariant over channels.
    float tap[IROWS][3];
    #pragma unroll
    for (int r = 0; r < IROWS; r++) {
        tap[r][0] = sIn[r][t];
        tap[r][1] = sIn[r][t + 1];
        tap[r][2] = sIn[r][t + 2];
    }

    const long ofs = (long)(c0) * PLANE_ + (long)h0 * WOUT_ + t;
    const float* bp = bias + ofs;
    float*       op = out + (long)b * COUT_ * PLANE_ + ofs;

    #pragma unroll 2
    for (int c = 0; c < CPER; c++) {
        const float4 wA = *reinterpret_cast<const float4*>(&sW[c * 12]);     // w0..w3
        const float4 wB = *reinterpret_cast<const float4*>(&sW[c * 12 + 4]); // w4..w7
        const float  w8 = sW[c * 12 + 8];

        #pragma unroll
        for (int r = 0; r < RPB; r++) {
            float y = tap[r][0] * wA.x;
            y = fmaf(tap[r    ][1], wA.y, y);
            y = fmaf(tap[r    ][2], wA.z, y);
            y = fmaf(tap[r + 1][0], wA.w, y);
            y = fmaf(tap[r + 1][1], wB.x, y);
            y = fmaf(tap[r + 1][2], wB.y, y);
            y = fmaf(tap[r + 2][0], wB.z, y);
            y = fmaf(tap[r + 2][1], wB.w, y);
            y = fmaf(tap[r + 2][2], w8,  y);
            y += __ldg(bp + r * WOUT_);
            op[r * WOUT_] = fmaxf(y, 0.0f);
        }
        bp += PLANE_;
        op += PLANE_;
    }
}

extern "C" void kernel_launch(void* const* d_in, const int* in_sizes, int n_in,
                              void* d_out, int out_size)
{
    const float* x    = (const float*)d_in[0];
    const float* Wt   = (const float*)d_in[1];
    const float* bias = (const float*)d_in[2];
    float*       out  = (float*)d_out;

    dim3 grid(HOUT_ / RPB, B_, CSPLIT);   // 37 x 16 x 2 = 1184 CTAs
    dim3 block(224);                      // 7 warps
    conv_bias_relu_kernel<<<grid, block>>>(x, Wt, bias, out);
}

// round 4
// speedup vs baseline: 3.0400x; 3.0400x over previous
#include <cuda_runtime.h>

// x1:   (16, 1, 224, 224) fp32
// W:    (288, 1, 3, 3)    fp32
// bias: (1, 288, 222, 222) fp32
// out:  (16, 288, 222, 222) fp32 = relu(conv_valid(x1, W) + bias)

#define B_      16
#define COUT_   288
#define CSPLIT  2
#define CPER    (COUT_ / CSPLIT)    // 144 channels per CTA
#define HIN_    224
#define WIN_    224
#define HOUT_   222
#define WOUT_   222
#define PLANE_  (HOUT_ * WOUT_)     // 49284
#define RPB     3                   // output rows per CTA (222 = 74*3)
#define IROWS   (RPB + 2)           // 5 input rows

__global__ __launch_bounds__(224, 6) void conv_bias_relu_kernel(
    const float* __restrict__ x,
    const float* __restrict__ Wt,
    const float* __restrict__ bias,
    float* __restrict__ out)
{
    // Weights padded to 12 floats/channel: per channel = 2x LDS.128 + 1x LDS.32.
    __shared__ __align__(16) float sW[CPER * 12];    // 6912 B
    __shared__ float sIn[IROWS][WIN_];               // 4480 B

    const int hg = blockIdx.x;            // 0..73  (row group)
    const int b  = blockIdx.y;            // 0..15
    const int cg = blockIdx.z;            // 0..1   (channel half)
    const int t  = threadIdx.x;           // 0..223
    const int h0 = hg * RPB;
    const int c0 = cg * CPER;

    // Cooperative weight load (this CTA's 144 channels) with 9->12 padding.
    const float* wsrc = Wt + c0 * 9;
    for (int i = t; i < CPER * 9; i += 224) {
        int c = i / 9, j = i - c * 9;
        sW[c * 12 + j] = wsrc[i];
    }

    // Cooperative load of the 5 input rows this CTA needs (each thread = 1 col).
    const float* xb = x + (long)b * HIN_ * WIN_;
    #pragma unroll
    for (int r = 0; r < IROWS; r++) sIn[r][t] = xb[(h0 + r) * WIN_ + t];

    __syncthreads();

    if (t >= WOUT_) return;

    // 15 taps in registers: rows h0..h0+4, cols t..t+2. Invariant over channels.
    float tap[IROWS][3];
    #pragma unroll
    for (int r = 0; r < IROWS; r++) {
        tap[r][0] = sIn[r][t];
        tap[r][1] = sIn[r][t + 1];
        tap[r][2] = sIn[r][t + 2];
    }

    const long ofs = (long)c0 * PLANE_ + (long)h0 * WOUT_ + t;
    const float* bp = bias + ofs;
    float*       op = out + (long)b * COUT_ * PLANE_ + ofs;

    // Bias double-buffer: prefetch channel c+1 while computing channel c.
    float bnx[RPB];
    #pragma unroll
    for (int r = 0; r < RPB; r++) bnx[r] = __ldg(bp + r * WOUT_);

    for (int c = 0; c < CPER; c++) {
        const float4 wA = *reinterpret_cast<const float4*>(&sW[c * 12]);     // w0..w3
        const float4 wB = *reinterpret_cast<const float4*>(&sW[c * 12 + 4]); // w4..w7
        const float  w8 = sW[c * 12 + 8];

        float bcur[RPB];
        #pragma unroll
        for (int r = 0; r < RPB; r++) bcur[r] = bnx[r];

        if (c + 1 < CPER) {
            bp += PLANE_;
            #pragma unroll
            for (int r = 0; r < RPB; r++) bnx[r] = __ldg(bp + r * WOUT_);
        }

        #pragma unroll
        for (int r = 0; r < RPB; r++) {
            float y = tap[r][0] * wA.x;
            y = fmaf(tap[r    ][1], wA.y, y);
            y = fmaf(tap[r    ][2], wA.z, y);
            y = fmaf(tap[r + 1][0], wA.w, y);
            y = fmaf(tap[r + 1][1], wB.x, y);
            y = fmaf(tap[r + 1][2], wB.y, y);
            y = fmaf(tap[r + 2][0], wB.z, y);
            y = fmaf(tap[r + 2][1], wB.w, y);
            y = fmaf(tap[r + 2][2], w8,  y);
            y += bcur[r];
            op[r * WOUT_] = fmaxf(y, 0.0f);
        }
        op += PLANE_;
    }
}

extern "C" void kernel_launch(void* const* d_in, const int* in_sizes, int n_in,
                              void* d_out, int out_size)
{
    const float* x    = (const float*)d_in[0];
    const float* Wt   = (const float*)d_in[1];
    const float* bias = (const float*)d_in[2];
    float*       out  = (float*)d_out;

    dim3 grid(HOUT_ / RPB, B_, CSPLIT);   // 74 x 16 x 2 = 2368 CTAs
    dim3 block(224);                      // 7 warps
    conv_bias_relu_kernel<<<grid, block>>>(x, Wt, bias, out);
}